// round 15
// baseline (speedup 1.0000x reference)
#include <cuda_runtime.h>
#include <cuda_fp16.h>
#include <math.h>
#include <stdint.h>

#define BB     2
#define SS     1024
#define TT     (BB*SS)
#define HID    2048
#define NH     32
#define HD     64
#define ROT    16
#define DFF    8192
#define LN_EPS 1e-5f

__device__ float g_q  [(size_t)TT * HID];
__device__ float g_kv [(size_t)TT * (2 * HID)];
__device__ float g_h  [(size_t)TT * HID];

__device__ __half g_a2[(size_t)TT * HID];
__device__ __half g_b2[(size_t)DFF * (2 * HID)];
__device__ __half g_c2[(size_t)TT * DFF];

__device__ __forceinline__ uint32_t smem_u32(const void* p) {
    uint32_t a;
    asm("{ .reg .u64 t; cvta.to.shared.u64 t, %1; cvt.u32.u64 %0, t; }"
        : "=r"(a) : "l"(p));
    return a;
}

#define CP_ASYNC16(sa, ga) \
    asm volatile("cp.async.cg.shared.global [%0], [%1], 16;" :: "r"(sa), "l"(ga))
#define CP_COMMIT() asm volatile("cp.async.commit_group;")
#define CP_WAIT1()  asm volatile("cp.async.wait_group 1;")

#define LDSM4(r, addr) \
    asm volatile("ldmatrix.sync.aligned.m8n8.x4.shared.b16 {%0,%1,%2,%3}, [%4];" \
        : "=r"((r)[0]), "=r"((r)[1]), "=r"((r)[2]), "=r"((r)[3]) : "r"(addr))

#define LDSM4T(r, addr) \
    asm volatile("ldmatrix.sync.aligned.m8n8.x4.trans.shared.b16 {%0,%1,%2,%3}, [%4];" \
        : "=r"((r)[0]), "=r"((r)[1]), "=r"((r)[2]), "=r"((r)[3]) : "r"(addr))

#define MMA16816(d, a, b0, b1) \
    asm volatile("mma.sync.aligned.m16n8k16.row.col.f32.f16.f16.f32 " \
        "{%0,%1,%2,%3}, {%4,%5,%6,%7}, {%8,%9}, {%0,%1,%2,%3};" \
        : "+f"((d)[0]), "+f"((d)[1]), "+f"((d)[2]), "+f"((d)[3]) \
        : "r"((a)[0]), "r"((a)[1]), "r"((a)[2]), "r"((a)[3]), "r"(b0), "r"(b1))

__device__ __forceinline__ uint32_t pack_h2(float a, float b) {
    uint32_t h0 = (uint32_t)__half_as_ushort(__float2half_rn(a));
    uint32_t h1 = (uint32_t)__half_as_ushort(__float2half_rn(b));
    return h0 | (h1 << 16);
}

// ---------------------------------------------------------------------------
// HMMA fp16 GEMM:  C[M,N] = A[M,K2] * B[N,K2]^T
// 128x128 tile, BK=64, 3-stage cp.async (spread over kk), 256 thr = 8 warps
// (2x4), warp tile 64x32, fragment double buffering, 2 CTAs/SM (4 warps/SMSP).
// mode 0: C fp32   mode 1: C = acc + add
// mode 4: interleaved gate/up -> silu(even)*odd -> fp16 out2 (width N/2)
// ---------------------------------------------------------------------------
#define GSTAGES      3
#define GTILE_BYTES  16384
#define GSTAGE_BYTES (2 * GTILE_BYTES)
#define GEMM_DSMEM   (GSTAGES * GSTAGE_BYTES)   // 96 KB

__global__ void __launch_bounds__(256, 2) gemm2_kernel(
    const __half* __restrict__ A, const __half* __restrict__ B,
    const float* __restrict__ add, float* __restrict__ C,
    __half* __restrict__ out2,
    int M, int N, int K2, int mode)
{
    extern __shared__ __align__(128) char smem[];
    const uint32_t smem_base = smem_u32(smem);

    const int tid  = threadIdx.x;
    const int lane = tid & 31;
    const int warp = tid >> 5;
    const int wm = warp >> 2;        // 0..1 (64 rows)
    const int wn = warp & 3;         // 0..3 (32 cols)
    const int bx = blockIdx.x, by = blockIdx.y;
    const int nk = K2 >> 6;

    // A+B: 2048 chunks total, 8/thread (4 A + 4 B)
    int lrow[4], lswz[4];
#pragma unroll
    for (int p = 0; p < 4; p++) {
        const int id = p * 256 + tid;
        const int row = id >> 3, c = id & 7;
        lrow[p] = row;
        lswz[p] = row * 128 + ((c ^ (row & 7)) << 4);
    }
    const __half* Abase = A + (size_t)(by * 128) * K2;
    const __half* Bbase = B + (size_t)(bx * 128) * K2;

    float acc[4][4][4];
#pragma unroll
    for (int i = 0; i < 4; i++)
#pragma unroll
        for (int j = 0; j < 4; j++)
#pragma unroll
            for (int r = 0; r < 4; r++) acc[i][j][r] = 0.f;

    // part 0..3: one A chunk + one B chunk each
    auto load_part = [&](int ks, int buf, int part) {
        const uint32_t sa = smem_base + buf * GSTAGE_BYTES;
        const uint32_t sb = sa + GTILE_BYTES;
        const int koff = ks * 64;
        const int p = part;
        const int c = (p * 256 + tid) & 7;
        CP_ASYNC16(sa + lswz[p], Abase + (size_t)lrow[p] * K2 + koff + c * 8);
        CP_ASYNC16(sb + lswz[p], Bbase + (size_t)lrow[p] * K2 + koff + c * 8);
    };

#pragma unroll
    for (int part = 0; part < 4; part++) load_part(0, 0, part);
    CP_COMMIT();
#pragma unroll
    for (int part = 0; part < 4; part++) load_part(1, 1, part);
    CP_COMMIT();

    for (int ks = 0; ks < nk; ks++) {
        CP_WAIT1();
        __syncthreads();

        const int buf = ks % GSTAGES;
        const uint32_t sa = smem_base + buf * GSTAGE_BYTES;
        const uint32_t sb = sa + GTILE_BYTES;
        const bool pf = (ks + 2 < nk);
        const int pbuf = (ks + 2) % GSTAGES;

        uint32_t ra[2][4][4], rb[2][2][4];

        auto ldfrag = [&](int kk, int pb) {
#pragma unroll
            for (int mt = 0; mt < 4; mt++) {
                const int row = wm * 64 + mt * 16 + (lane & 15);
                const int ch  = kk * 2 + (lane >> 4);
                LDSM4(ra[pb][mt], sa + row * 128 + ((ch ^ (row & 7)) << 4));
            }
#pragma unroll
            for (int p = 0; p < 2; p++) {
                const int n  = wn * 32 + p * 16 + (lane & 7) + ((lane >> 4) << 3);
                const int ch = kk * 2 + ((lane >> 3) & 1);
                LDSM4(rb[pb][p], sb + n * 128 + ((ch ^ (n & 7)) << 4));
            }
        };

        ldfrag(0, 0);
#pragma unroll
        for (int kk = 0; kk < 4; kk++) {
            const int cur = kk & 1;
            if (kk < 3) ldfrag(kk + 1, cur ^ 1);
            if (pf) load_part(ks + 2, pbuf, kk);
#pragma unroll
            for (int mt = 0; mt < 4; mt++)
#pragma unroll
                for (int nt = 0; nt < 4; nt++)
                    MMA16816(acc[mt][nt], ra[cur][mt],
                             rb[cur][nt >> 1][(nt & 1) * 2],
                             rb[cur][nt >> 1][(nt & 1) * 2 + 1]);
        }
        CP_COMMIT();
    }

    const int r0 = lane >> 2;
    const int c0 = (lane & 3) * 2;
#pragma unroll
    for (int mt = 0; mt < 4; mt++) {
#pragma unroll
        for (int half_ = 0; half_ < 2; half_++) {
            const int row = by * 128 + wm * 64 + mt * 16 + r0 + half_ * 8;
            const int colb = bx * 128 + wn * 32;
            if (mode == 4) {
                __half* Or = out2 + (size_t)row * (N >> 1);
#pragma unroll
                for (int nt = 0; nt < 4; nt++) {
                    float g = acc[mt][nt][half_ * 2];
                    const float u = acc[mt][nt][half_ * 2 + 1];
                    g = g / (1.f + expf(-g)) * u;
                    Or[(colb + nt * 8 + c0) >> 1] = __float2half_rn(g);
                }
            } else {
                float* Cr = C + (size_t)row * N + colb;
                const float* Ar = (mode == 1) ? add + (size_t)row * N + colb : nullptr;
#pragma unroll
                for (int nt = 0; nt < 4; nt++) {
                    float2 o;
                    o.x = acc[mt][nt][half_ * 2];
                    o.y = acc[mt][nt][half_ * 2 + 1];
                    if (Ar) {
                        const float2 av = *(const float2*)(Ar + nt * 8 + c0);
                        o.x += av.x; o.y += av.y;
                    }
                    *(float2*)(Cr + nt * 8 + c0) = o;
                }
            }
        }
    }
}

// ---------------------------------------------------------------------------
// Flash attention (unchanged)
// ---------------------------------------------------------------------------
#define QS_STRIDE 136
#define VS_STRIDE 72
#define FA_SMEM   (2*(128*QS_STRIDE*2) + 128*VS_STRIDE*2)

__global__ void __launch_bounds__(256, 2) flash_attn_kernel(
    const float* __restrict__ q, const float* __restrict__ kbase,
    const float* __restrict__ vbase, const float* __restrict__ mask,
    __half* __restrict__ ctxh, int kvs)
{
    extern __shared__ __align__(128) char smem[];
    __half* Qs = (__half*)smem;
    __half* Ks = Qs + 128 * QS_STRIDE;
    __half* Vs = Ks + 128 * QS_STRIDE;
    const uint32_t QsB = smem_u32(Qs);
    const uint32_t KsB = smem_u32(Ks);
    const uint32_t VsB = smem_u32(Vs);

    const int tid  = threadIdx.x;
    const int lane = tid & 31;
    const int w    = tid >> 5;
    const int bh = blockIdx.y;
    const int b = bh >> 5, h = bh & 31;
    const int q0 = blockIdx.x * 128;

#pragma unroll
    for (int p = 0; p < 8; p++) {
        const int id = p * 256 + tid;
        const int row = id >> 4;
        const int c4  = (id & 15) * 4;
        const float4 vv = *(const float4*)(q + (size_t)(b * SS + q0 + row) * HID + h * HD + c4);
        uint2 hi, lo;
        hi.x = pack_h2(vv.x, vv.y); hi.y = pack_h2(vv.z, vv.w);
        lo.x = pack_h2(vv.x - __half2float(__float2half_rn(vv.x)),
                       vv.y - __half2float(__float2half_rn(vv.y)));
        lo.y = pack_h2(vv.z - __half2float(__float2half_rn(vv.z)),
                       vv.w - __half2float(__float2half_rn(vv.w)));
        *(uint2*)(Qs + row * QS_STRIDE + c4)      = hi;
        *(uint2*)(Qs + row * QS_STRIDE + 64 + c4) = lo;
    }

    float sc[64];
    float o[8][4];
#pragma unroll
    for (int j = 0; j < 8; j++)
#pragma unroll
        for (int r = 0; r < 4; r++) o[j][r] = 0.f;
    float mrow[2] = {-INFINITY, -INFINITY};
    float lrow[2] = {0.f, 0.f};

    const int rA = lane >> 2;
    const int cA = (lane & 3) * 2;

    for (int kt = 0; kt < SS / 128; kt++) {
        __syncthreads();
#pragma unroll
        for (int p = 0; p < 8; p++) {
            const int id = p * 256 + tid;
            const int row = id >> 4;
            const int c4  = (id & 15) * 4;
            const float4 vv = *(const float4*)(kbase + (size_t)(b * SS + kt * 128 + row) * kvs + h * HD + c4);
            uint2 hi;
            hi.x = pack_h2(vv.x, vv.y); hi.y = pack_h2(vv.z, vv.w);
            *(uint2*)(Ks + row * QS_STRIDE + c4)      = hi;
            *(uint2*)(Ks + row * QS_STRIDE + 64 + c4) = hi;
        }
#pragma unroll
        for (int p = 0; p < 8; p++) {
            const int id = p * 256 + tid;
            const int krow = id >> 4;
            const int c4   = (id & 15) * 4;
            const float4 vv = *(const float4*)(vbase + (size_t)(b * SS + kt * 128 + krow) * kvs + h * HD + c4);
            uint2 hi;
            hi.x = pack_h2(vv.x, vv.y); hi.y = pack_h2(vv.z, vv.w);
            *(uint2*)(Vs + krow * VS_STRIDE + c4) = hi;
        }
        __syncthreads();

#pragma unroll
        for (int i = 0; i < 64; i++) sc[i] = 0.f;
#pragma unroll
        for (int s = 0; s < 8; s++) {
            uint32_t ra[4];
            const int arow2 = 16 * w + (lane & 15);
            LDSM4(ra, QsB + (arow2 * QS_STRIDE + s * 16 + ((lane >> 4) << 3)) * 2);
#pragma unroll
            for (int t2 = 0; t2 < 8; t2++) {
                uint32_t rb[4];
                const int n  = t2 * 16 + (lane & 7) + ((lane >> 4) << 3);
                const int cb = s * 16 + (((lane >> 3) & 1) << 3);
                LDSM4(rb, KsB + (n * QS_STRIDE + cb) * 2);
                MMA16816((sc + (2 * t2) * 4),     ra, rb[0], rb[1]);
                MMA16816((sc + (2 * t2 + 1) * 4), ra, rb[2], rb[3]);
            }
        }

        const int qrA = q0 + 16 * w + rA;
        const int qrB = qrA + 8;
        float tm[2] = {-INFINITY, -INFINITY};
#pragma unroll
        for (int t = 0; t < 16; t++) {
            const int kc = kt * 128 + t * 8 + cA;
            const float2 mA = *(const float2*)(mask + ((size_t)b * SS + qrA) * SS + kc);
            const float2 mB = *(const float2*)(mask + ((size_t)b * SS + qrB) * SS + kc);
            sc[t * 4 + 0] = sc[t * 4 + 0] * 0.125f + mA.x;
            sc[t * 4 + 1] = sc[t * 4 + 1] * 0.125f + mA.y;
            sc[t * 4 + 2] = sc[t * 4 + 2] * 0.125f + mB.x;
            sc[t * 4 + 3] = sc[t * 4 + 3] * 0.125f + mB.y;
            tm[0] = fmaxf(tm[0], fmaxf(sc[t * 4 + 0], sc[t * 4 + 1]));
            tm[1] = fmaxf(tm[1], fmaxf(sc[t * 4 + 2], sc[t * 4 + 3]));
        }
#pragma unroll
        for (int off = 1; off <= 2; off <<= 1) {
            tm[0] = fmaxf(tm[0], __shfl_xor_sync(0xffffffffu, tm[0], off));
            tm[1] = fmaxf(tm[1], __shfl_xor_sync(0xffffffffu, tm[1], off));
        }
        const float mn0 = fmaxf(mrow[0], tm[0]);
        const float mn1 = fmaxf(mrow[1], tm[1]);
        const float e0 = __expf(mrow[0] - mn0);
        const float e1 = __expf(mrow[1] - mn1);
        float ts[2] = {0.f, 0.f};
#pragma unroll
        for (int t = 0; t < 16; t++) {
            sc[t * 4 + 0] = __expf(sc[t * 4 + 0] - mn0);
            sc[t * 4 + 1] = __expf(sc[t * 4 + 1] - mn0);
            sc[t * 4 + 2] = __expf(sc[t * 4 + 2] - mn1);
            sc[t * 4 + 3] = __expf(sc[t * 4 + 3] - mn1);
            ts[0] += sc[t * 4 + 0] + sc[t * 4 + 1];
            ts[1] += sc[t * 4 + 2] + sc[t * 4 + 3];
        }
#pragma unroll
        for (int off = 1; off <= 2; off <<= 1) {
            ts[0] += __shfl_xor_sync(0xffffffffu, ts[0], off);
            ts[1] += __shfl_xor_sync(0xffffffffu, ts[1], off);
        }
        lrow[0] = lrow[0] * e0 + ts[0];
        lrow[1] = lrow[1] * e1 + ts[1];
        mrow[0] = mn0; mrow[1] = mn1;
#pragma unroll
        for (int j = 0; j < 8; j++) {
            o[j][0] *= e0; o[j][1] *= e0;
            o[j][2] *= e1; o[j][3] *= e1;
        }

#pragma unroll
        for (int s2 = 0; s2 < 8; s2++) {
            const float p00 = sc[(2 * s2) * 4 + 0], p01 = sc[(2 * s2) * 4 + 1];
            const float p10 = sc[(2 * s2) * 4 + 2], p11 = sc[(2 * s2) * 4 + 3];
            const float r00 = sc[(2 * s2 + 1) * 4 + 0], r01 = sc[(2 * s2 + 1) * 4 + 1];
            const float r10 = sc[(2 * s2 + 1) * 4 + 2], r11 = sc[(2 * s2 + 1) * 4 + 3];
            uint32_t ph[4], pl[4];
            ph[0] = pack_h2(p00, p01); ph[1] = pack_h2(p10, p11);
            ph[2] = pack_h2(r00, r01); ph[3] = pack_h2(r10, r11);
            pl[0] = pack_h2(p00 - __half2float(__float2half_rn(p00)),
                            p01 - __half2float(__float2half_rn(p01)));
            pl[1] = pack_h2(p10 - __half2float(__float2half_rn(p10)),
                            p11 - __half2float(__float2half_rn(p11)));
            pl[2] = pack_h2(r00 - __half2float(__float2half_rn(r00)),
                            r01 - __half2float(__float2half_rn(r01)));
            pl[3] = pack_h2(r10 - __half2float(__float2half_rn(r10)),
                            r11 - __half2float(__float2half_rn(r11)));
            const int krow = s2 * 16 + (lane & 7) + (((lane >> 3) & 1) << 3);
#pragma unroll
            for (int dt = 0; dt < 4; dt++) {
                uint32_t bh_[4];
                LDSM4T(bh_, VsB + (krow * VS_STRIDE + dt * 16 + ((lane >> 4) << 3)) * 2);
                MMA16816(o[2 * dt],     ph, bh_[0], bh_[1]);
                MMA16816(o[2 * dt + 1], ph, bh_[2], bh_[3]);
                MMA16816(o[2 * dt],     pl, bh_[0], bh_[1]);
                MMA16816(o[2 * dt + 1], pl, bh_[2], bh_[3]);
            }
        }
    }

    const float inv0 = 1.f / lrow[0];
    const float inv1 = 1.f / lrow[1];
    const size_t tokA = (size_t)(b * SS + q0 + 16 * w + rA);
    const size_t tokB = tokA + 8;
#pragma unroll
    for (int j = 0; j < 8; j++) {
        const int cg = h * HD + j * 8 + cA;
        ctxh[tokA * HID + cg]     = __float2half_rn(o[j][0] * inv0);
        ctxh[tokA * HID + cg + 1] = __float2half_rn(o[j][1] * inv0);
        ctxh[tokB * HID + cg]     = __float2half_rn(o[j][2] * inv1);
        ctxh[tokB * HID + cg + 1] = __float2half_rn(o[j][3] * inv1);
    }
}

__global__ void __launch_bounds__(256) conv4_kernel(
    const float* __restrict__ X0, const float* __restrict__ X1,
    const float* __restrict__ X2, const float* __restrict__ X3,
    __half* __restrict__ Y)
{
    const float* X = (blockIdx.y == 0) ? X0 : (blockIdx.y == 1) ? X1 :
                     (blockIdx.y == 2) ? X2 : X3;
    __half* Yb = Y + (size_t)blockIdx.y * ((size_t)HID * HID);
    const size_t i0 = ((size_t)blockIdx.x * 256 + threadIdx.x) * 4;
    const size_t st = (size_t)gridDim.x * 1024;
    float4 v[8];
#pragma unroll
    for (int qq = 0; qq < 8; qq++) v[qq] = *(const float4*)(X + i0 + qq * st);
#pragma unroll
    for (int qq = 0; qq < 8; qq++) {
        uint2 hp;
        hp.x = pack_h2(v[qq].x, v[qq].y);
        hp.y = pack_h2(v[qq].z, v[qq].w);
        *(uint2*)(Yb + i0 + qq * st) = hp;
    }
}

__global__ void __launch_bounds__(256) conv_kernel(
    const float* __restrict__ X, __half* __restrict__ Y)
{
    const size_t i0 = ((size_t)blockIdx.x * 256 + threadIdx.x) * 4;
    const size_t st = (size_t)gridDim.x * 1024;
    float4 v[8];
#pragma unroll
    for (int qq = 0; qq < 8; qq++) v[qq] = *(const float4*)(X + i0 + qq * st);
#pragma unroll
    for (int qq = 0; qq < 8; qq++) {
        uint2 hp;
        hp.x = pack_h2(v[qq].x, v[qq].y);
        hp.y = pack_h2(v[qq].z, v[qq].w);
        *(uint2*)(Y + i0 + qq * st) = hp;
    }
}

__global__ void __launch_bounds__(256) conv_il2_kernel(
    const float* __restrict__ Xg, const float* __restrict__ Xu,
    __half* __restrict__ Y)
{
    const float* X = blockIdx.y ? Xu : Xg;
    const int parity = blockIdx.y;
    const size_t i0 = ((size_t)blockIdx.x * 256 + threadIdx.x) * 4;
    const size_t st = (size_t)gridDim.x * 1024;
    float4 v[8];
#pragma unroll
    for (int qq = 0; qq < 8; qq++) v[qq] = *(const float4*)(X + i0 + qq * st);
#pragma unroll
    for (int qq = 0; qq < 8; qq++) {
        const size_t e = i0 + qq * st;
        const size_t row = e >> 11;
        const size_t col = e & 2047;
        uint2 hp;
        hp.x = pack_h2(v[qq].x, v[qq].y);
        hp.y = pack_h2(v[qq].z, v[qq].w);
        *(uint2*)(Y + ((2 * row + parity) << 11) + col) = hp;
    }
}

__global__ void __launch_bounds__(256) layernorm_h_kernel(
    const float* __restrict__ x, const float* __restrict__ w,
    const float* __restrict__ b, __half* __restrict__ outh)
{
    const int t   = blockIdx.x;
    const int tid = threadIdx.x;
    const float* xr = x + (size_t)t * HID;

    float v[8];
    float s = 0.f, s2 = 0.f;
#pragma unroll
    for (int i = 0; i < 8; i++) {
        v[i] = xr[tid + i * 256];
        s  += v[i];
        s2 += v[i] * v[i];
    }
#pragma unroll
    for (int o = 16; o; o >>= 1) {
        s  += __shfl_xor_sync(0xffffffffu, s,  o);
        s2 += __shfl_xor_sync(0xffffffffu, s2, o);
    }
    __shared__ float ss[8], ss2[8];
    if ((tid & 31) == 0) { ss[tid >> 5] = s; ss2[tid >> 5] = s2; }
    __syncthreads();
    if (tid < 32) {
        s  = (tid < 8) ? ss [tid] : 0.f;
        s2 = (tid < 8) ? ss2[tid] : 0.f;
#pragma unroll
        for (int o = 4; o; o >>= 1) {
            s  += __shfl_xor_sync(0xffffffffu, s,  o);
            s2 += __shfl_xor_sync(0xffffffffu, s2, o);
        }
        if (tid == 0) { ss[0] = s; ss2[0] = s2; }
    }
    __syncthreads();
    const float mean = ss[0] * (1.f / HID);
    const float var  = ss2[0] * (1.f / HID) - mean * mean;
    const float rstd = rsqrtf(var + LN_EPS);
    __half* orow = outh + (size_t)t * HID;
#pragma unroll
    for (int i = 0; i < 8; i++) {
        const int idx = tid + i * 256;
        const float y = (v[i] - mean) * rstd * w[idx] + b[idx];
        orow[idx] = __float2half_rn(y);
    }
}

__global__ void __launch_bounds__(256) rope_kernel(
    float* __restrict__ q, float* __restrict__ k,
    const int* __restrict__ pos_ids, int kvs)
{
    const int idx = blockIdx.x * blockDim.x + threadIdx.x;
    if (idx >= TT * NH * 8) return;
    const int i = idx & 7;
    const int h = (idx >> 3) & 31;
    const int t = idx >> 8;
    const int b = t / SS, s = t % SS;
    const int pos = pos_ids[b * SS + s];

    const float freq = powf(10000.0f, -(2.0f * (float)i) / (float)ROT);
    const float ang  = (float)pos * freq;
    float c, si;
    sincosf(ang, &si, &c);

    {
        const size_t base = (size_t)t * HID + h * HD;
        float q0 = q[base + i], q1 = q[base + i + 8];
        q[base + i]     = q0 * c - q1 * si;
        q[base + i + 8] = q1 * c + q0 * si;
    }
    {
        const size_t base = (size_t)t * kvs + h * HD;
        float k0 = k[base + i], k1 = k[base + i + 8];
        k[base + i]     = k0 * c - k1 * si;
        k[base + i + 8] = k1 * c + k0 * si;
    }
}

extern "C" void kernel_launch(void* const* d_in, const int* in_sizes, int n_in,
                              void* d_out, int out_size)
{
    const float* hidden = (const float*)d_in[0];
    const float* memory = (const float*)d_in[1];
    const float* mask   = (const float*)d_in[2];
    const int*   pos    = (const int*)  d_in[3];
    const float* Wq     = (const float*)d_in[4];
    const float* Wk     = (const float*)d_in[5];
    const float* Wv     = (const float*)d_in[6];
    const float* Wo     = (const float*)d_in[7];
    const float* ln1w   = (const float*)d_in[8];
    const float* ln1b   = (const float*)d_in[9];
    const float* ln2w   = (const float*)d_in[10];
    const float* ln2b   = (const float*)d_in[11];
    const float* gw     = (const float*)d_in[12];
    const float* uw     = (const float*)d_in[13];
    const float* dw     = (const float*)d_in[14];
    float* out = (float*)d_out;

    float *q, *kv, *h;
    __half *a2, *b2, *c2;
    cudaGetSymbolAddress((void**)&q,    g_q);
    cudaGetSymbolAddress((void**)&kv,   g_kv);
    cudaGetSymbolAddress((void**)&h,    g_h);
    cudaGetSymbolAddress((void**)&a2,   g_a2);
    cudaGetSymbolAddress((void**)&b2,   g_b2);
    cudaGetSymbolAddress((void**)&c2,   g_c2);

    cudaFuncSetAttribute(gemm2_kernel,
                         cudaFuncAttributeMaxDynamicSharedMemorySize, GEMM_DSMEM);
    cudaFuncSetAttribute(flash_attn_kernel,
                         cudaFuncAttributeMaxDynamicSharedMemorySize, FA_SMEM);

    const size_t HH = (size_t)HID * HID;

    auto gemm = [&](const __half* A, const __half* B,
                    const float* add, float* C, __half* O2,
                    int M, int N, int K2, int mode) {
        gemm2_kernel<<<dim3(N / 128, M / 128), 256, GEMM_DSMEM>>>(
            A, B, add, C, O2, M, N, K2, mode);
    };

    conv4_kernel<<<dim3((unsigned)(HH / 8192), 4), 256>>>(Wq, Wk, Wv, Wo, b2);
    conv_kernel<<<(unsigned)((size_t)TT * HID / 8192), 256>>>(memory, c2);
    layernorm_h_kernel<<<TT, 256>>>(hidden, ln1w, ln1b, a2);

    gemm(a2, b2, nullptr, q, nullptr, TT, HID, HID, 0);
    gemm(c2, b2 + HH, nullptr, kv, nullptr, TT, 2 * HID, HID, 0);

    rope_kernel<<<(TT * NH * 8) / 256, 256>>>(q, kv, pos, 2 * HID);

    flash_attn_kernel<<<dim3(SS / 128, BB * NH), 256, FA_SMEM>>>(
        q, kv, kv + HID, mask, a2, 2 * HID);

    gemm(a2, b2 + 3 * HH, hidden, h, nullptr, TT, HID, HID, 1);

    layernorm_h_kernel<<<TT, 256>>>(h, ln2w, ln2b, a2);

    conv_il2_kernel<<<dim3((unsigned)((size_t)DFF * HID / 8192), 2), 256>>>(gw, uw, b2);
    gemm(a2, b2, nullptr, nullptr, c2, TT, 2 * DFF, HID, 4);
    conv_kernel<<<(unsigned)((size_t)HID * DFF / 8192), 256>>>(dw, b2);
    gemm(c2, b2, h, out, nullptr, TT, HID, DFF, 1);
}

// round 16
// speedup vs baseline: 1.3721x; 1.3721x over previous
#include <cuda_runtime.h>
#include <cuda_fp16.h>
#include <math.h>
#include <stdint.h>

#define BB     2
#define SS     1024
#define TT     (BB*SS)
#define HID    2048
#define NH     32
#define HD     64
#define ROT    16
#define DFF    8192
#define LN_EPS 1e-5f

__device__ float g_q  [(size_t)TT * HID];
__device__ float g_kv [(size_t)TT * (2 * HID)];
__device__ float g_h  [(size_t)TT * HID];

__device__ __half g_a2[(size_t)TT * HID];
__device__ __half g_b2[(size_t)DFF * (2 * HID)];
__device__ __half g_c2[(size_t)TT * DFF];

__device__ __forceinline__ uint32_t smem_u32(const void* p) {
    uint32_t a;
    asm("{ .reg .u64 t; cvta.to.shared.u64 t, %1; cvt.u32.u64 %0, t; }"
        : "=r"(a) : "l"(p));
    return a;
}

#define CP_ASYNC16(sa, ga) \
    asm volatile("cp.async.cg.shared.global [%0], [%1], 16;" :: "r"(sa), "l"(ga))
#define CP_COMMIT() asm volatile("cp.async.commit_group;")
#define CP_WAIT1()  asm volatile("cp.async.wait_group 1;")

#define LDSM4(r, addr) \
    asm volatile("ldmatrix.sync.aligned.m8n8.x4.shared.b16 {%0,%1,%2,%3}, [%4];" \
        : "=r"((r)[0]), "=r"((r)[1]), "=r"((r)[2]), "=r"((r)[3]) : "r"(addr))

#define LDSM4T(r, addr) \
    asm volatile("ldmatrix.sync.aligned.m8n8.x4.trans.shared.b16 {%0,%1,%2,%3}, [%4];" \
        : "=r"((r)[0]), "=r"((r)[1]), "=r"((r)[2]), "=r"((r)[3]) : "r"(addr))

#define MMA16816(d, a, b0, b1) \
    asm volatile("mma.sync.aligned.m16n8k16.row.col.f32.f16.f16.f32 " \
        "{%0,%1,%2,%3}, {%4,%5,%6,%7}, {%8,%9}, {%0,%1,%2,%3};" \
        : "+f"((d)[0]), "+f"((d)[1]), "+f"((d)[2]), "+f"((d)[3]) \
        : "r"((a)[0]), "r"((a)[1]), "r"((a)[2]), "r"((a)[3]), "r"(b0), "r"(b1))

__device__ __forceinline__ uint32_t pack_h2(float a, float b) {
    uint32_t h0 = (uint32_t)__half_as_ushort(__float2half_rn(a));
    uint32_t h1 = (uint32_t)__half_as_ushort(__float2half_rn(b));
    return h0 | (h1 << 16);
}

// ---------------------------------------------------------------------------
// HMMA fp16 GEMM (R13 config): C[M,N] = A[M,K2] * B[N,K2]^T
// 128x128 tile, BK=64, 3-stage cp.async spread over kk, 128 thr = 4 warps,
// warp tile 64x64, fragment double buffering, 2 CTAs/SM.
// mode 0: C fp32   mode 1: C = acc + add
// mode 4: interleaved gate/up -> silu(even)*odd -> fp16 out2 (width N/2)
// ---------------------------------------------------------------------------
#define GSTAGES      3
#define GTILE_BYTES  16384
#define GSTAGE_BYTES (2 * GTILE_BYTES)
#define GEMM_DSMEM   (GSTAGES * GSTAGE_BYTES)

__global__ void __launch_bounds__(128, 2) gemm2_kernel(
    const __half* __restrict__ A, const __half* __restrict__ B,
    const float* __restrict__ add, float* __restrict__ C,
    __half* __restrict__ out2,
    int M, int N, int K2, int mode)
{
    extern __shared__ __align__(128) char smem[];
    const uint32_t smem_base = smem_u32(smem);

    const int tid  = threadIdx.x;
    const int lane = tid & 31;
    const int warp = tid >> 5;
    const int wm = warp >> 1;
    const int wn = warp & 1;
    const int bx = blockIdx.x, by = blockIdx.y;
    const int nk = K2 >> 6;

    int lrow[8], lswz[8];
#pragma unroll
    for (int p = 0; p < 8; p++) {
        const int id = p * 128 + tid;
        const int row = id >> 3;
        const int c   = id & 7;
        lrow[p] = row;
        lswz[p] = row * 128 + ((c ^ (row & 7)) << 4);
    }
    const __half* Abase = A + (size_t)(by * 128) * K2;
    const __half* Bbase = B + (size_t)(bx * 128) * K2;

    float acc[4][8][4];
#pragma unroll
    for (int i = 0; i < 4; i++)
#pragma unroll
        for (int j = 0; j < 8; j++)
#pragma unroll
            for (int r = 0; r < 4; r++) acc[i][j][r] = 0.f;

    auto load_part = [&](int ks, int buf, int part) {
        const uint32_t sa = smem_base + buf * GSTAGE_BYTES;
        const uint32_t sb = sa + GTILE_BYTES;
        const int koff = ks * 64;
#pragma unroll
        for (int pp = 0; pp < 2; pp++) {
            const int p = part * 2 + pp;
            const int c = (p * 128 + tid) & 7;
            CP_ASYNC16(sa + lswz[p], Abase + (size_t)lrow[p] * K2 + koff + c * 8);
            CP_ASYNC16(sb + lswz[p], Bbase + (size_t)lrow[p] * K2 + koff + c * 8);
        }
    };

#pragma unroll
    for (int part = 0; part < 4; part++) load_part(0, 0, part);
    CP_COMMIT();
#pragma unroll
    for (int part = 0; part < 4; part++) load_part(1, 1, part);
    CP_COMMIT();

    for (int ks = 0; ks < nk; ks++) {
        CP_WAIT1();
        __syncthreads();

        const int buf = ks % GSTAGES;
        const uint32_t sa = smem_base + buf * GSTAGE_BYTES;
        const uint32_t sb = sa + GTILE_BYTES;
        const bool pf = (ks + 2 < nk);
        const int pbuf = (ks + 2) % GSTAGES;

        uint32_t ra[2][4][4], rb[2][4][4];

        auto ldfrag = [&](int kk, int pb) {
#pragma unroll
            for (int mt = 0; mt < 4; mt++) {
                const int row = wm * 64 + mt * 16 + (lane & 15);
                const int ch  = kk * 2 + (lane >> 4);
                LDSM4(ra[pb][mt], sa + row * 128 + ((ch ^ (row & 7)) << 4));
            }
#pragma unroll
            for (int p = 0; p < 4; p++) {
                const int n  = wn * 64 + p * 16 + (lane & 7) + ((lane >> 4) << 3);
                const int ch = kk * 2 + ((lane >> 3) & 1);
                LDSM4(rb[pb][p], sb + n * 128 + ((ch ^ (n & 7)) << 4));
            }
        };

        ldfrag(0, 0);
#pragma unroll
        for (int kk = 0; kk < 4; kk++) {
            const int cur = kk & 1;
            if (kk < 3) ldfrag(kk + 1, cur ^ 1);
            if (pf) load_part(ks + 2, pbuf, kk);
#pragma unroll
            for (int mt = 0; mt < 4; mt++)
#pragma unroll
                for (int nt = 0; nt < 8; nt++)
                    MMA16816(acc[mt][nt], ra[cur][mt],
                             rb[cur][nt >> 1][(nt & 1) * 2],
                             rb[cur][nt >> 1][(nt & 1) * 2 + 1]);
        }
        CP_COMMIT();
    }

    const int r0 = lane >> 2;
    const int c0 = (lane & 3) * 2;
#pragma unroll
    for (int mt = 0; mt < 4; mt++) {
#pragma unroll
        for (int half_ = 0; half_ < 2; half_++) {
            const int row = by * 128 + wm * 64 + mt * 16 + r0 + half_ * 8;
            const int colb = bx * 128 + wn * 64;
            if (mode == 4) {
                __half* Or = out2 + (size_t)row * (N >> 1);
#pragma unroll
                for (int nt = 0; nt < 8; nt++) {
                    float g = acc[mt][nt][half_ * 2];
                    const float u = acc[mt][nt][half_ * 2 + 1];
                    g = g / (1.f + expf(-g)) * u;
                    Or[(colb + nt * 8 + c0) >> 1] = __float2half_rn(g);
                }
            } else {
                float* Cr = C + (size_t)row * N + colb;
                const float* Ar = (mode == 1) ? add + (size_t)row * N + colb : nullptr;
#pragma unroll
                for (int nt = 0; nt < 8; nt++) {
                    float2 o;
                    o.x = acc[mt][nt][half_ * 2];
                    o.y = acc[mt][nt][half_ * 2 + 1];
                    if (Ar) {
                        const float2 av = *(const float2*)(Ar + nt * 8 + c0);
                        o.x += av.x; o.y += av.y;
                    }
                    *(float2*)(Cr + nt * 8 + c0) = o;
                }
            }
        }
    }
}

// ---------------------------------------------------------------------------
// Flash attention, fp16 HMMA, 2-term QK and PV, fp32 online softmax.
// V row-major [k][d], B-fragments via ldmatrix.trans. 2 CTAs/SM.
// ---------------------------------------------------------------------------
#define QS_STRIDE 136
#define VS_STRIDE 72
#define FA_SMEM   (2*(128*QS_STRIDE*2) + 128*VS_STRIDE*2)

__global__ void __launch_bounds__(256, 2) flash_attn_kernel(
    const float* __restrict__ q, const float* __restrict__ kbase,
    const float* __restrict__ vbase, const float* __restrict__ mask,
    __half* __restrict__ ctxh, int kvs)
{
    extern __shared__ __align__(128) char smem[];
    __half* Qs = (__half*)smem;
    __half* Ks = Qs + 128 * QS_STRIDE;
    __half* Vs = Ks + 128 * QS_STRIDE;
    const uint32_t QsB = smem_u32(Qs);
    const uint32_t KsB = smem_u32(Ks);
    const uint32_t VsB = smem_u32(Vs);

    const int tid  = threadIdx.x;
    const int lane = tid & 31;
    const int w    = tid >> 5;
    const int bh = blockIdx.y;
    const int b = bh >> 5, h = bh & 31;
    const int q0 = blockIdx.x * 128;

#pragma unroll
    for (int p = 0; p < 8; p++) {
        const int id = p * 256 + tid;
        const int row = id >> 4;
        const int c4  = (id & 15) * 4;
        const float4 vv = *(const float4*)(q + (size_t)(b * SS + q0 + row) * HID + h * HD + c4);
        uint2 hi, lo;
        hi.x = pack_h2(vv.x, vv.y); hi.y = pack_h2(vv.z, vv.w);
        lo.x = pack_h2(vv.x - __half2float(__float2half_rn(vv.x)),
                       vv.y - __half2float(__float2half_rn(vv.y)));
        lo.y = pack_h2(vv.z - __half2float(__float2half_rn(vv.z)),
                       vv.w - __half2float(__float2half_rn(vv.w)));
        *(uint2*)(Qs + row * QS_STRIDE + c4)      = hi;
        *(uint2*)(Qs + row * QS_STRIDE + 64 + c4) = lo;
    }

    float sc[64];
    float o[8][4];
#pragma unroll
    for (int j = 0; j < 8; j++)
#pragma unroll
        for (int r = 0; r < 4; r++) o[j][r] = 0.f;
    float mrow[2] = {-INFINITY, -INFINITY};
    float lrow[2] = {0.f, 0.f};

    const int rA = lane >> 2;
    const int cA = (lane & 3) * 2;

    for (int kt = 0; kt < SS / 128; kt++) {
        __syncthreads();
#pragma unroll
        for (int p = 0; p < 8; p++) {
            const int id = p * 256 + tid;
            const int row = id >> 4;
            const int c4  = (id & 15) * 4;
            const float4 vv = *(const float4*)(kbase + (size_t)(b * SS + kt * 128 + row) * kvs + h * HD + c4);
            uint2 hi;
            hi.x = pack_h2(vv.x, vv.y); hi.y = pack_h2(vv.z, vv.w);
            *(uint2*)(Ks + row * QS_STRIDE + c4)      = hi;
            *(uint2*)(Ks + row * QS_STRIDE + 64 + c4) = hi;
        }
#pragma unroll
        for (int p = 0; p < 8; p++) {
            const int id = p * 256 + tid;
            const int krow = id >> 4;
            const int c4   = (id & 15) * 4;
            const float4 vv = *(const float4*)(vbase + (size_t)(b * SS + kt * 128 + krow) * kvs + h * HD + c4);
            uint2 hi;
            hi.x = pack_h2(vv.x, vv.y); hi.y = pack_h2(vv.z, vv.w);
            *(uint2*)(Vs + krow * VS_STRIDE + c4) = hi;
        }
        __syncthreads();

#pragma unroll
        for (int i = 0; i < 64; i++) sc[i] = 0.f;
#pragma unroll
        for (int s = 0; s < 8; s++) {
            uint32_t ra[4];
            const int arow2 = 16 * w + (lane & 15);
            LDSM4(ra, QsB + (arow2 * QS_STRIDE + s * 16 + ((lane >> 4) << 3)) * 2);
#pragma unroll
            for (int t2 = 0; t2 < 8; t2++) {
                uint32_t rb[4];
                const int n  = t2 * 16 + (lane & 7) + ((lane >> 4) << 3);
                const int cb = s * 16 + (((lane >> 3) & 1) << 3);
                LDSM4(rb, KsB + (n * QS_STRIDE + cb) * 2);
                MMA16816((sc + (2 * t2) * 4),     ra, rb[0], rb[1]);
                MMA16816((sc + (2 * t2 + 1) * 4), ra, rb[2], rb[3]);
            }
        }

        const int qrA = q0 + 16 * w + rA;
        const int qrB = qrA + 8;
        float tm[2] = {-INFINITY, -INFINITY};
#pragma unroll
        for (int t = 0; t < 16; t++) {
            const int kc = kt * 128 + t * 8 + cA;
            const float2 mA = *(const float2*)(mask + ((size_t)b * SS + qrA) * SS + kc);
            const float2 mB = *(const float2*)(mask + ((size_t)b * SS + qrB) * SS + kc);
            sc[t * 4 + 0] = sc[t * 4 + 0] * 0.125f + mA.x;
            sc[t * 4 + 1] = sc[t * 4 + 1] * 0.125f + mA.y;
            sc[t * 4 + 2] = sc[t * 4 + 2] * 0.125f + mB.x;
            sc[t * 4 + 3] = sc[t * 4 + 3] * 0.125f + mB.y;
            tm[0] = fmaxf(tm[0], fmaxf(sc[t * 4 + 0], sc[t * 4 + 1]));
            tm[1] = fmaxf(tm[1], fmaxf(sc[t * 4 + 2], sc[t * 4 + 3]));
        }
#pragma unroll
        for (int off = 1; off <= 2; off <<= 1) {
            tm[0] = fmaxf(tm[0], __shfl_xor_sync(0xffffffffu, tm[0], off));
            tm[1] = fmaxf(tm[1], __shfl_xor_sync(0xffffffffu, tm[1], off));
        }
        const float mn0 = fmaxf(mrow[0], tm[0]);
        const float mn1 = fmaxf(mrow[1], tm[1]);
        const float e0 = __expf(mrow[0] - mn0);
        const float e1 = __expf(mrow[1] - mn1);
        float ts[2] = {0.f, 0.f};
#pragma unroll
        for (int t = 0; t < 16; t++) {
            sc[t * 4 + 0] = __expf(sc[t * 4 + 0] - mn0);
            sc[t * 4 + 1] = __expf(sc[t * 4 + 1] - mn0);
            sc[t * 4 + 2] = __expf(sc[t * 4 + 2] - mn1);
            sc[t * 4 + 3] = __expf(sc[t * 4 + 3] - mn1);
            ts[0] += sc[t * 4 + 0] + sc[t * 4 + 1];
            ts[1] += sc[t * 4 + 2] + sc[t * 4 + 3];
        }
#pragma unroll
        for (int off = 1; off <= 2; off <<= 1) {
            ts[0] += __shfl_xor_sync(0xffffffffu, ts[0], off);
            ts[1] += __shfl_xor_sync(0xffffffffu, ts[1], off);
        }
        lrow[0] = lrow[0] * e0 + ts[0];
        lrow[1] = lrow[1] * e1 + ts[1];
        mrow[0] = mn0; mrow[1] = mn1;
#pragma unroll
        for (int j = 0; j < 8; j++) {
            o[j][0] *= e0; o[j][1] *= e0;
            o[j][2] *= e1; o[j][3] *= e1;
        }

#pragma unroll
        for (int s2 = 0; s2 < 8; s2++) {
            const float p00 = sc[(2 * s2) * 4 + 0], p01 = sc[(2 * s2) * 4 + 1];
            const float p10 = sc[(2 * s2) * 4 + 2], p11 = sc[(2 * s2) * 4 + 3];
            const float r00 = sc[(2 * s2 + 1) * 4 + 0], r01 = sc[(2 * s2 + 1) * 4 + 1];
            const float r10 = sc[(2 * s2 + 1) * 4 + 2], r11 = sc[(2 * s2 + 1) * 4 + 3];
            uint32_t ph[4], pl[4];
            ph[0] = pack_h2(p00, p01); ph[1] = pack_h2(p10, p11);
            ph[2] = pack_h2(r00, r01); ph[3] = pack_h2(r10, r11);
            pl[0] = pack_h2(p00 - __half2float(__float2half_rn(p00)),
                            p01 - __half2float(__float2half_rn(p01)));
            pl[1] = pack_h2(p10 - __half2float(__float2half_rn(p10)),
                            p11 - __half2float(__float2half_rn(p11)));
            pl[2] = pack_h2(r00 - __half2float(__float2half_rn(r00)),
                            r01 - __half2float(__float2half_rn(r01)));
            pl[3] = pack_h2(r10 - __half2float(__float2half_rn(r10)),
                            r11 - __half2float(__float2half_rn(r11)));
            const int krow = s2 * 16 + (lane & 7) + (((lane >> 3) & 1) << 3);
#pragma unroll
            for (int dt = 0; dt < 4; dt++) {
                uint32_t bh_[4];
                LDSM4T(bh_, VsB + (krow * VS_STRIDE + dt * 16 + ((lane >> 4) << 3)) * 2);
                MMA16816(o[2 * dt],     ph, bh_[0], bh_[1]);
                MMA16816(o[2 * dt + 1], ph, bh_[2], bh_[3]);
                MMA16816(o[2 * dt],     pl, bh_[0], bh_[1]);
                MMA16816(o[2 * dt + 1], pl, bh_[2], bh_[3]);
            }
        }
    }

    const float inv0 = 1.f / lrow[0];
    const float inv1 = 1.f / lrow[1];
    const size_t tokA = (size_t)(b * SS + q0 + 16 * w + rA);
    const size_t tokB = tokA + 8;
#pragma unroll
    for (int j = 0; j < 8; j++) {
        const int cg = h * HD + j * 8 + cA;
        ctxh[tokA * HID + cg]     = __float2half_rn(o[j][0] * inv0);
        ctxh[tokA * HID + cg + 1] = __float2half_rn(o[j][1] * inv0);
        ctxh[tokB * HID + cg]     = __float2half_rn(o[j][2] * inv1);
        ctxh[tokB * HID + cg + 1] = __float2half_rn(o[j][3] * inv1);
    }
}

__global__ void __launch_bounds__(256) conv4_kernel(
    const float* __restrict__ X0, const float* __restrict__ X1,
    const float* __restrict__ X2, const float* __restrict__ X3,
    __half* __restrict__ Y)
{
    const float* X = (blockIdx.y == 0) ? X0 : (blockIdx.y == 1) ? X1 :
                     (blockIdx.y == 2) ? X2 : X3;
    __half* Yb = Y + (size_t)blockIdx.y * ((size_t)HID * HID);
    const size_t i0 = ((size_t)blockIdx.x * 256 + threadIdx.x) * 4;
    const size_t st = (size_t)gridDim.x * 1024;
    float4 v[8];
#pragma unroll
    for (int qq = 0; qq < 8; qq++) v[qq] = *(const float4*)(X + i0 + qq * st);
#pragma unroll
    for (int qq = 0; qq < 8; qq++) {
        uint2 hp;
        hp.x = pack_h2(v[qq].x, v[qq].y);
        hp.y = pack_h2(v[qq].z, v[qq].w);
        *(uint2*)(Yb + i0 + qq * st) = hp;
    }
}

__global__ void __launch_bounds__(256) conv_kernel(
    const float* __restrict__ X, __half* __restrict__ Y)
{
    const size_t i0 = ((size_t)blockIdx.x * 256 + threadIdx.x) * 4;
    const size_t st = (size_t)gridDim.x * 1024;
    float4 v[8];
#pragma unroll
    for (int qq = 0; qq < 8; qq++) v[qq] = *(const float4*)(X + i0 + qq * st);
#pragma unroll
    for (int qq = 0; qq < 8; qq++) {
        uint2 hp;
        hp.x = pack_h2(v[qq].x, v[qq].y);
        hp.y = pack_h2(v[qq].z, v[qq].w);
        *(uint2*)(Y + i0 + qq * st) = hp;
    }
}

__global__ void __launch_bounds__(256) conv_il2_kernel(
    const float* __restrict__ Xg, const float* __restrict__ Xu,
    __half* __restrict__ Y)
{
    const float* X = blockIdx.y ? Xu : Xg;
    const int parity = blockIdx.y;
    const size_t i0 = ((size_t)blockIdx.x * 256 + threadIdx.x) * 4;
    const size_t st = (size_t)gridDim.x * 1024;
    float4 v[8];
#pragma unroll
    for (int qq = 0; qq < 8; qq++) v[qq] = *(const float4*)(X + i0 + qq * st);
#pragma unroll
    for (int qq = 0; qq < 8; qq++) {
        const size_t e = i0 + qq * st;
        const size_t row = e >> 11;
        const size_t col = e & 2047;
        uint2 hp;
        hp.x = pack_h2(v[qq].x, v[qq].y);
        hp.y = pack_h2(v[qq].z, v[qq].w);
        *(uint2*)(Y + ((2 * row + parity) << 11) + col) = hp;
    }
}

__global__ void __launch_bounds__(256) layernorm_h_kernel(
    const float* __restrict__ x, const float* __restrict__ w,
    const float* __restrict__ b, __half* __restrict__ outh)
{
    const int t   = blockIdx.x;
    const int tid = threadIdx.x;
    const float* xr = x + (size_t)t * HID;

    float v[8];
    float s = 0.f, s2 = 0.f;
#pragma unroll
    for (int i = 0; i < 8; i++) {
        v[i] = xr[tid + i * 256];
        s  += v[i];
        s2 += v[i] * v[i];
    }
#pragma unroll
    for (int o = 16; o; o >>= 1) {
        s  += __shfl_xor_sync(0xffffffffu, s,  o);
        s2 += __shfl_xor_sync(0xffffffffu, s2, o);
    }
    __shared__ float ss[8], ss2[8];
    if ((tid & 31) == 0) { ss[tid >> 5] = s; ss2[tid >> 5] = s2; }
    __syncthreads();
    if (tid < 32) {
        s  = (tid < 8) ? ss [tid] : 0.f;
        s2 = (tid < 8) ? ss2[tid] : 0.f;
#pragma unroll
        for (int o = 4; o; o >>= 1) {
            s  += __shfl_xor_sync(0xffffffffu, s,  o);
            s2 += __shfl_xor_sync(0xffffffffu, s2, o);
        }
        if (tid == 0) { ss[0] = s; ss2[0] = s2; }
    }
    __syncthreads();
    const float mean = ss[0] * (1.f / HID);
    const float var  = ss2[0] * (1.f / HID) - mean * mean;
    const float rstd = rsqrtf(var + LN_EPS);
    __half* orow = outh + (size_t)t * HID;
#pragma unroll
    for (int i = 0; i < 8; i++) {
        const int idx = tid + i * 256;
        const float y = (v[i] - mean) * rstd * w[idx] + b[idx];
        orow[idx] = __float2half_rn(y);
    }
}

__global__ void __launch_bounds__(256) rope_kernel(
    float* __restrict__ q, float* __restrict__ k,
    const int* __restrict__ pos_ids, int kvs)
{
    const int idx = blockIdx.x * blockDim.x + threadIdx.x;
    if (idx >= TT * NH * 8) return;
    const int i = idx & 7;
    const int h = (idx >> 3) & 31;
    const int t = idx >> 8;
    const int b = t / SS, s = t % SS;
    const int pos = pos_ids[b * SS + s];

    const float freq = powf(10000.0f, -(2.0f * (float)i) / (float)ROT);
    const float ang  = (float)pos * freq;
    float c, si;
    sincosf(ang, &si, &c);

    {
        const size_t base = (size_t)t * HID + h * HD;
        float q0 = q[base + i], q1 = q[base + i + 8];
        q[base + i]     = q0 * c - q1 * si;
        q[base + i + 8] = q1 * c + q0 * si;
    }
    {
        const size_t base = (size_t)t * kvs + h * HD;
        float k0 = k[base + i], k1 = k[base + i + 8];
        k[base + i]     = k0 * c - k1 * si;
        k[base + i + 8] = k1 * c + k0 * si;
    }
}

extern "C" void kernel_launch(void* const* d_in, const int* in_sizes, int n_in,
                              void* d_out, int out_size)
{
    const float* hidden = (const float*)d_in[0];
    const float* memory = (const float*)d_in[1];
    const float* mask   = (const float*)d_in[2];
    const int*   pos    = (const int*)  d_in[3];
    const float* Wq     = (const float*)d_in[4];
    const float* Wk     = (const float*)d_in[5];
    const float* Wv     = (const float*)d_in[6];
    const float* Wo     = (const float*)d_in[7];
    const float* ln1w   = (const float*)d_in[8];
    const float* ln1b   = (const float*)d_in[9];
    const float* ln2w   = (const float*)d_in[10];
    const float* ln2b   = (const float*)d_in[11];
    const float* gw     = (const float*)d_in[12];
    const float* uw     = (const float*)d_in[13];
    const float* dw     = (const float*)d_in[14];
    float* out = (float*)d_out;

    float *q, *kv, *h;
    __half *a2, *b2, *c2;
    cudaGetSymbolAddress((void**)&q,    g_q);
    cudaGetSymbolAddress((void**)&kv,   g_kv);
    cudaGetSymbolAddress((void**)&h,    g_h);
    cudaGetSymbolAddress((void**)&a2,   g_a2);
    cudaGetSymbolAddress((void**)&b2,   g_b2);
    cudaGetSymbolAddress((void**)&c2,   g_c2);

    cudaFuncSetAttribute(gemm2_kernel,
                         cudaFuncAttributeMaxDynamicSharedMemorySize, GEMM_DSMEM);
    cudaFuncSetAttribute(flash_attn_kernel,
                         cudaFuncAttributeMaxDynamicSharedMemorySize, FA_SMEM);

    const size_t HH = (size_t)HID * HID;

    auto gemm = [&](const __half* A, const __half* B,
                    const float* add, float* C, __half* O2,
                    int M, int N, int K2, int mode) {
        gemm2_kernel<<<dim3(N / 128, M / 128), 128, GEMM_DSMEM>>>(
            A, B, add, C, O2, M, N, K2, mode);
    };

    conv4_kernel<<<dim3((unsigned)(HH / 8192), 4), 256>>>(Wq, Wk, Wv, Wo, b2);
    conv_kernel<<<(unsigned)((size_t)TT * HID / 8192), 256>>>(memory, c2);
    layernorm_h_kernel<<<TT, 256>>>(hidden, ln1w, ln1b, a2);

    gemm(a2, b2, nullptr, q, nullptr, TT, HID, HID, 0);
    gemm(c2, b2 + HH, nullptr, kv, nullptr, TT, 2 * HID, HID, 0);

    rope_kernel<<<(TT * NH * 8) / 256, 256>>>(q, kv, pos, 2 * HID);

    flash_attn_kernel<<<dim3(SS / 128, BB * NH), 256, FA_SMEM>>>(
        q, kv, kv + HID, mask, a2, 2 * HID);

    gemm(a2, b2 + 3 * HH, hidden, h, nullptr, TT, HID, HID, 1);

    layernorm_h_kernel<<<TT, 256>>>(h, ln2w, ln2b, a2);

    conv_il2_kernel<<<dim3((unsigned)((size_t)DFF * HID / 8192), 2), 256>>>(gw, uw, b2);
    gemm(a2, b2, nullptr, nullptr, c2, TT, 2 * DFF, HID, 4);
    conv_kernel<<<(unsigned)((size_t)HID * DFF / 8192), 256>>>(dw, b2);
    gemm(c2, b2, h, out, nullptr, TT, HID, DFF, 1);
}

// round 17
// speedup vs baseline: 1.4546x; 1.0601x over previous
#include <cuda_runtime.h>
#include <cuda_fp16.h>
#include <math.h>
#include <stdint.h>

#define BB     2
#define SS     1024
#define TT     (BB*SS)
#define HID    2048
#define NH     32
#define HD     64
#define ROT    16
#define DFF    8192
#define LN_EPS 1e-5f

__device__ float g_h  [(size_t)TT * HID];

__device__ __half g_q2 [(size_t)TT * HID];
__device__ __half g_kv2[(size_t)TT * (2 * HID)];
__device__ __half g_a2 [(size_t)TT * HID];
__device__ __half g_b2 [(size_t)DFF * (2 * HID)];
__device__ __half g_c2 [(size_t)TT * DFF];

__device__ __forceinline__ uint32_t smem_u32(const void* p) {
    uint32_t a;
    asm("{ .reg .u64 t; cvta.to.shared.u64 t, %1; cvt.u32.u64 %0, t; }"
        : "=r"(a) : "l"(p));
    return a;
}

#define CP_ASYNC16(sa, ga) \
    asm volatile("cp.async.cg.shared.global [%0], [%1], 16;" :: "r"(sa), "l"(ga))
#define CP_COMMIT() asm volatile("cp.async.commit_group;")
#define CP_WAIT1()  asm volatile("cp.async.wait_group 1;")

#define LDSM4(r, addr) \
    asm volatile("ldmatrix.sync.aligned.m8n8.x4.shared.b16 {%0,%1,%2,%3}, [%4];" \
        : "=r"((r)[0]), "=r"((r)[1]), "=r"((r)[2]), "=r"((r)[3]) : "r"(addr))

#define LDSM4T(r, addr) \
    asm volatile("ldmatrix.sync.aligned.m8n8.x4.trans.shared.b16 {%0,%1,%2,%3}, [%4];" \
        : "=r"((r)[0]), "=r"((r)[1]), "=r"((r)[2]), "=r"((r)[3]) : "r"(addr))

#define MMA16816(d, a, b0, b1) \
    asm volatile("mma.sync.aligned.m16n8k16.row.col.f32.f16.f16.f32 " \
        "{%0,%1,%2,%3}, {%4,%5,%6,%7}, {%8,%9}, {%0,%1,%2,%3};" \
        : "+f"((d)[0]), "+f"((d)[1]), "+f"((d)[2]), "+f"((d)[3]) \
        : "r"((a)[0]), "r"((a)[1]), "r"((a)[2]), "r"((a)[3]), "r"(b0), "r"(b1))

__device__ __forceinline__ uint32_t pack_h2(float a, float b) {
    uint32_t h0 = (uint32_t)__half_as_ushort(__float2half_rn(a));
    uint32_t h1 = (uint32_t)__half_as_ushort(__float2half_rn(b));
    return h0 | (h1 << 16);
}

// ---------------------------------------------------------------------------
// HMMA fp16 GEMM (R13 config): C[M,N] = A[M,K2] * B[N,K2]^T
// 128x128 tile, BK=64, 3-stage cp.async spread over kk, 128 thr = 4 warps,
// warp tile 64x64, fragment double buffering, 2 CTAs/SM.
// mode 0: C fp32   mode 1: C = acc + add   mode 5: C fp16 (out2, stride N)
// mode 4: interleaved gate/up -> silu(even)*odd -> fp16 out2 (width N/2)
// ---------------------------------------------------------------------------
#define GSTAGES      3
#define GTILE_BYTES  16384
#define GSTAGE_BYTES (2 * GTILE_BYTES)
#define GEMM_DSMEM   (GSTAGES * GSTAGE_BYTES)

__global__ void __launch_bounds__(128, 2) gemm2_kernel(
    const __half* __restrict__ A, const __half* __restrict__ B,
    const float* __restrict__ add, float* __restrict__ C,
    __half* __restrict__ out2,
    int M, int N, int K2, int mode)
{
    extern __shared__ __align__(128) char smem[];
    const uint32_t smem_base = smem_u32(smem);

    const int tid  = threadIdx.x;
    const int lane = tid & 31;
    const int warp = tid >> 5;
    const int wm = warp >> 1;
    const int wn = warp & 1;
    const int bx = blockIdx.x, by = blockIdx.y;
    const int nk = K2 >> 6;

    int lrow[8], lswz[8];
#pragma unroll
    for (int p = 0; p < 8; p++) {
        const int id = p * 128 + tid;
        const int row = id >> 3;
        const int c   = id & 7;
        lrow[p] = row;
        lswz[p] = row * 128 + ((c ^ (row & 7)) << 4);
    }
    const __half* Abase = A + (size_t)(by * 128) * K2;
    const __half* Bbase = B + (size_t)(bx * 128) * K2;

    float acc[4][8][4];
#pragma unroll
    for (int i = 0; i < 4; i++)
#pragma unroll
        for (int j = 0; j < 8; j++)
#pragma unroll
            for (int r = 0; r < 4; r++) acc[i][j][r] = 0.f;

    auto load_part = [&](int ks, int buf, int part) {
        const uint32_t sa = smem_base + buf * GSTAGE_BYTES;
        const uint32_t sb = sa + GTILE_BYTES;
        const int koff = ks * 64;
#pragma unroll
        for (int pp = 0; pp < 2; pp++) {
            const int p = part * 2 + pp;
            const int c = (p * 128 + tid) & 7;
            CP_ASYNC16(sa + lswz[p], Abase + (size_t)lrow[p] * K2 + koff + c * 8);
            CP_ASYNC16(sb + lswz[p], Bbase + (size_t)lrow[p] * K2 + koff + c * 8);
        }
    };

#pragma unroll
    for (int part = 0; part < 4; part++) load_part(0, 0, part);
    CP_COMMIT();
#pragma unroll
    for (int part = 0; part < 4; part++) load_part(1, 1, part);
    CP_COMMIT();

    for (int ks = 0; ks < nk; ks++) {
        CP_WAIT1();
        __syncthreads();

        const int buf = ks % GSTAGES;
        const uint32_t sa = smem_base + buf * GSTAGE_BYTES;
        const uint32_t sb = sa + GTILE_BYTES;
        const bool pf = (ks + 2 < nk);
        const int pbuf = (ks + 2) % GSTAGES;

        uint32_t ra[2][4][4], rb[2][4][4];

        auto ldfrag = [&](int kk, int pb) {
#pragma unroll
            for (int mt = 0; mt < 4; mt++) {
                const int row = wm * 64 + mt * 16 + (lane & 15);
                const int ch  = kk * 2 + (lane >> 4);
                LDSM4(ra[pb][mt], sa + row * 128 + ((ch ^ (row & 7)) << 4));
            }
#pragma unroll
            for (int p = 0; p < 4; p++) {
                const int n  = wn * 64 + p * 16 + (lane & 7) + ((lane >> 4) << 3);
                const int ch = kk * 2 + ((lane >> 3) & 1);
                LDSM4(rb[pb][p], sb + n * 128 + ((ch ^ (n & 7)) << 4));
            }
        };

        ldfrag(0, 0);
#pragma unroll
        for (int kk = 0; kk < 4; kk++) {
            const int cur = kk & 1;
            if (kk < 3) ldfrag(kk + 1, cur ^ 1);
            if (pf) load_part(ks + 2, pbuf, kk);
#pragma unroll
            for (int mt = 0; mt < 4; mt++)
#pragma unroll
                for (int nt = 0; nt < 8; nt++)
                    MMA16816(acc[mt][nt], ra[cur][mt],
                             rb[cur][nt >> 1][(nt & 1) * 2],
                             rb[cur][nt >> 1][(nt & 1) * 2 + 1]);
        }
        CP_COMMIT();
    }

    const int r0 = lane >> 2;
    const int c0 = (lane & 3) * 2;
#pragma unroll
    for (int mt = 0; mt < 4; mt++) {
#pragma unroll
        for (int half_ = 0; half_ < 2; half_++) {
            const int row = by * 128 + wm * 64 + mt * 16 + r0 + half_ * 8;
            const int colb = bx * 128 + wn * 64;
            if (mode == 4) {
                __half* Or = out2 + (size_t)row * (N >> 1);
#pragma unroll
                for (int nt = 0; nt < 8; nt++) {
                    float g = acc[mt][nt][half_ * 2];
                    const float u = acc[mt][nt][half_ * 2 + 1];
                    g = g / (1.f + expf(-g)) * u;
                    Or[(colb + nt * 8 + c0) >> 1] = __float2half_rn(g);
                }
            } else if (mode == 5) {
                __half* Or = out2 + (size_t)row * N + colb;
#pragma unroll
                for (int nt = 0; nt < 8; nt++)
                    *(uint32_t*)(Or + nt * 8 + c0) =
                        pack_h2(acc[mt][nt][half_ * 2], acc[mt][nt][half_ * 2 + 1]);
            } else {
                float* Cr = C + (size_t)row * N + colb;
                const float* Ar = (mode == 1) ? add + (size_t)row * N + colb : nullptr;
#pragma unroll
                for (int nt = 0; nt < 8; nt++) {
                    float2 o;
                    o.x = acc[mt][nt][half_ * 2];
                    o.y = acc[mt][nt][half_ * 2 + 1];
                    if (Ar) {
                        const float2 av = *(const float2*)(Ar + nt * 8 + c0);
                        o.x += av.x; o.y += av.y;
                    }
                    *(float2*)(Cr + nt * 8 + c0) = o;
                }
            }
        }
    }
}

// ---------------------------------------------------------------------------
// Flash attention, fp16 in/out. QK 1-term (K=64), PV 2-term (Ph+Pl).
// Q/K/V smem fills are raw uint2 copies. V row-major, LDSM4T. 2 CTAs/SM.
// ---------------------------------------------------------------------------
#define QSS    72      // 64 data + 8 pad (fp16 elems)
#define FA_SMEM (3 * 128 * QSS * 2)   // 55296 B

__global__ void __launch_bounds__(256, 2) flash_attn_kernel(
    const __half* __restrict__ q2, const __half* __restrict__ kbase,
    const __half* __restrict__ vbase, const float* __restrict__ mask,
    __half* __restrict__ ctxh, int kvs)
{
    extern __shared__ __align__(128) char smem[];
    __half* Qs = (__half*)smem;
    __half* Ks = Qs + 128 * QSS;
    __half* Vs = Ks + 128 * QSS;
    const uint32_t QsB = smem_u32(Qs);
    const uint32_t KsB = smem_u32(Ks);
    const uint32_t VsB = smem_u32(Vs);

    const int tid  = threadIdx.x;
    const int lane = tid & 31;
    const int w    = tid >> 5;
    const int bh = blockIdx.y;
    const int b = bh >> 5, h = bh & 31;
    const int q0 = blockIdx.x * 128;

    // ---- load Q tile once (plain fp16 copy) ----
#pragma unroll
    for (int p = 0; p < 8; p++) {
        const int id = p * 256 + tid;
        const int row = id >> 4;
        const int c4  = (id & 15) * 4;
        *(uint2*)(Qs + row * QSS + c4) =
            *(const uint2*)(q2 + (size_t)(b * SS + q0 + row) * HID + h * HD + c4);
    }

    float sc[64];
    float o[8][4];
#pragma unroll
    for (int j = 0; j < 8; j++)
#pragma unroll
        for (int r = 0; r < 4; r++) o[j][r] = 0.f;
    float mrow[2] = {-INFINITY, -INFINITY};
    float lrow[2] = {0.f, 0.f};

    const int rA = lane >> 2;
    const int cA = (lane & 3) * 2;

    for (int kt = 0; kt < SS / 128; kt++) {
        __syncthreads();
#pragma unroll
        for (int p = 0; p < 8; p++) {
            const int id = p * 256 + tid;
            const int row = id >> 4;
            const int c4  = (id & 15) * 4;
            *(uint2*)(Ks + row * QSS + c4) =
                *(const uint2*)(kbase + (size_t)(b * SS + kt * 128 + row) * kvs + h * HD + c4);
            *(uint2*)(Vs + row * QSS + c4) =
                *(const uint2*)(vbase + (size_t)(b * SS + kt * 128 + row) * kvs + h * HD + c4);
        }
        __syncthreads();

        // ---- scores: S = Q . K^T  (K=64, 1-term) ----
#pragma unroll
        for (int i = 0; i < 64; i++) sc[i] = 0.f;
#pragma unroll
        for (int s = 0; s < 4; s++) {
            uint32_t ra[4];
            const int arow2 = 16 * w + (lane & 15);
            LDSM4(ra, QsB + (arow2 * QSS + s * 16 + ((lane >> 4) << 3)) * 2);
#pragma unroll
            for (int t2 = 0; t2 < 8; t2++) {
                uint32_t rb[4];
                const int n  = t2 * 16 + (lane & 7) + ((lane >> 4) << 3);
                const int cb = s * 16 + (((lane >> 3) & 1) << 3);
                LDSM4(rb, KsB + (n * QSS + cb) * 2);
                MMA16816((sc + (2 * t2) * 4),     ra, rb[0], rb[1]);
                MMA16816((sc + (2 * t2 + 1) * 4), ra, rb[2], rb[3]);
            }
        }

        // ---- scale + mask, online softmax ----
        const int qrA = q0 + 16 * w + rA;
        const int qrB = qrA + 8;
        float tm[2] = {-INFINITY, -INFINITY};
#pragma unroll
        for (int t = 0; t < 16; t++) {
            const int kc = kt * 128 + t * 8 + cA;
            const float2 mA = *(const float2*)(mask + ((size_t)b * SS + qrA) * SS + kc);
            const float2 mB = *(const float2*)(mask + ((size_t)b * SS + qrB) * SS + kc);
            sc[t * 4 + 0] = sc[t * 4 + 0] * 0.125f + mA.x;
            sc[t * 4 + 1] = sc[t * 4 + 1] * 0.125f + mA.y;
            sc[t * 4 + 2] = sc[t * 4 + 2] * 0.125f + mB.x;
            sc[t * 4 + 3] = sc[t * 4 + 3] * 0.125f + mB.y;
            tm[0] = fmaxf(tm[0], fmaxf(sc[t * 4 + 0], sc[t * 4 + 1]));
            tm[1] = fmaxf(tm[1], fmaxf(sc[t * 4 + 2], sc[t * 4 + 3]));
        }
#pragma unroll
        for (int off = 1; off <= 2; off <<= 1) {
            tm[0] = fmaxf(tm[0], __shfl_xor_sync(0xffffffffu, tm[0], off));
            tm[1] = fmaxf(tm[1], __shfl_xor_sync(0xffffffffu, tm[1], off));
        }
        const float mn0 = fmaxf(mrow[0], tm[0]);
        const float mn1 = fmaxf(mrow[1], tm[1]);
        const float e0 = __expf(mrow[0] - mn0);
        const float e1 = __expf(mrow[1] - mn1);
        float ts[2] = {0.f, 0.f};
#pragma unroll
        for (int t = 0; t < 16; t++) {
            sc[t * 4 + 0] = __expf(sc[t * 4 + 0] - mn0);
            sc[t * 4 + 1] = __expf(sc[t * 4 + 1] - mn0);
            sc[t * 4 + 2] = __expf(sc[t * 4 + 2] - mn1);
            sc[t * 4 + 3] = __expf(sc[t * 4 + 3] - mn1);
            ts[0] += sc[t * 4 + 0] + sc[t * 4 + 1];
            ts[1] += sc[t * 4 + 2] + sc[t * 4 + 3];
        }
#pragma unroll
        for (int off = 1; off <= 2; off <<= 1) {
            ts[0] += __shfl_xor_sync(0xffffffffu, ts[0], off);
            ts[1] += __shfl_xor_sync(0xffffffffu, ts[1], off);
        }
        lrow[0] = lrow[0] * e0 + ts[0];
        lrow[1] = lrow[1] * e1 + ts[1];
        mrow[0] = mn0; mrow[1] = mn1;
#pragma unroll
        for (int j = 0; j < 8; j++) {
            o[j][0] *= e0; o[j][1] *= e0;
            o[j][2] *= e1; o[j][3] *= e1;
        }

        // ---- O += (Ph + Pl) . V ----
#pragma unroll
        for (int s2 = 0; s2 < 8; s2++) {
            const float p00 = sc[(2 * s2) * 4 + 0], p01 = sc[(2 * s2) * 4 + 1];
            const float p10 = sc[(2 * s2) * 4 + 2], p11 = sc[(2 * s2) * 4 + 3];
            const float r00 = sc[(2 * s2 + 1) * 4 + 0], r01 = sc[(2 * s2 + 1) * 4 + 1];
            const float r10 = sc[(2 * s2 + 1) * 4 + 2], r11 = sc[(2 * s2 + 1) * 4 + 3];
            uint32_t ph[4], pl[4];
            ph[0] = pack_h2(p00, p01); ph[1] = pack_h2(p10, p11);
            ph[2] = pack_h2(r00, r01); ph[3] = pack_h2(r10, r11);
            pl[0] = pack_h2(p00 - __half2float(__float2half_rn(p00)),
                            p01 - __half2float(__float2half_rn(p01)));
            pl[1] = pack_h2(p10 - __half2float(__float2half_rn(p10)),
                            p11 - __half2float(__float2half_rn(p11)));
            pl[2] = pack_h2(r00 - __half2float(__float2half_rn(r00)),
                            r01 - __half2float(__float2half_rn(r01)));
            pl[3] = pack_h2(r10 - __half2float(__float2half_rn(r10)),
                            r11 - __half2float(__float2half_rn(r11)));
            const int krow = s2 * 16 + (lane & 7) + (((lane >> 3) & 1) << 3);
#pragma unroll
            for (int dt = 0; dt < 4; dt++) {
                uint32_t bh_[4];
                LDSM4T(bh_, VsB + (krow * QSS + dt * 16 + ((lane >> 4) << 3)) * 2);
                MMA16816(o[2 * dt],     ph, bh_[0], bh_[1]);
                MMA16816(o[2 * dt + 1], ph, bh_[2], bh_[3]);
                MMA16816(o[2 * dt],     pl, bh_[0], bh_[1]);
                MMA16816(o[2 * dt + 1], pl, bh_[2], bh_[3]);
            }
        }
    }

    const float inv0 = 1.f / lrow[0];
    const float inv1 = 1.f / lrow[1];
    const size_t tokA = (size_t)(b * SS + q0 + 16 * w + rA);
    const size_t tokB = tokA + 8;
#pragma unroll
    for (int j = 0; j < 8; j++) {
        const int cg = h * HD + j * 8 + cA;
        *(uint32_t*)(ctxh + tokA * HID + cg) = pack_h2(o[j][0] * inv0, o[j][1] * inv0);
        *(uint32_t*)(ctxh + tokB * HID + cg) = pack_h2(o[j][2] * inv1, o[j][3] * inv1);
    }
}

__global__ void __launch_bounds__(256) conv4_kernel(
    const float* __restrict__ X0, const float* __restrict__ X1,
    const float* __restrict__ X2, const float* __restrict__ X3,
    __half* __restrict__ Y)
{
    const float* X = (blockIdx.y == 0) ? X0 : (blockIdx.y == 1) ? X1 :
                     (blockIdx.y == 2) ? X2 : X3;
    __half* Yb = Y + (size_t)blockIdx.y * ((size_t)HID * HID);
    const size_t i0 = ((size_t)blockIdx.x * 256 + threadIdx.x) * 4;
    const size_t st = (size_t)gridDim.x * 1024;
    float4 v[8];
#pragma unroll
    for (int qq = 0; qq < 8; qq++) v[qq] = *(const float4*)(X + i0 + qq * st);
#pragma unroll
    for (int qq = 0; qq < 8; qq++) {
        uint2 hp;
        hp.x = pack_h2(v[qq].x, v[qq].y);
        hp.y = pack_h2(v[qq].z, v[qq].w);
        *(uint2*)(Yb + i0 + qq * st) = hp;
    }
}

__global__ void __launch_bounds__(256) conv_kernel(
    const float* __restrict__ X, __half* __restrict__ Y)
{
    const size_t i0 = ((size_t)blockIdx.x * 256 + threadIdx.x) * 4;
    const size_t st = (size_t)gridDim.x * 1024;
    float4 v[8];
#pragma unroll
    for (int qq = 0; qq < 8; qq++) v[qq] = *(const float4*)(X + i0 + qq * st);
#pragma unroll
    for (int qq = 0; qq < 8; qq++) {
        uint2 hp;
        hp.x = pack_h2(v[qq].x, v[qq].y);
        hp.y = pack_h2(v[qq].z, v[qq].w);
        *(uint2*)(Y + i0 + qq * st) = hp;
    }
}

__global__ void __launch_bounds__(256) conv_il2_kernel(
    const float* __restrict__ Xg, const float* __restrict__ Xu,
    __half* __restrict__ Y)
{
    const float* X = blockIdx.y ? Xu : Xg;
    const int parity = blockIdx.y;
    const size_t i0 = ((size_t)blockIdx.x * 256 + threadIdx.x) * 4;
    const size_t st = (size_t)gridDim.x * 1024;
    float4 v[8];
#pragma unroll
    for (int qq = 0; qq < 8; qq++) v[qq] = *(const float4*)(X + i0 + qq * st);
#pragma unroll
    for (int qq = 0; qq < 8; qq++) {
        const size_t e = i0 + qq * st;
        const size_t row = e >> 11;
        const size_t col = e & 2047;
        uint2 hp;
        hp.x = pack_h2(v[qq].x, v[qq].y);
        hp.y = pack_h2(v[qq].z, v[qq].w);
        *(uint2*)(Y + ((2 * row + parity) << 11) + col) = hp;
    }
}

__global__ void __launch_bounds__(256) layernorm_h_kernel(
    const float* __restrict__ x, const float* __restrict__ w,
    const float* __restrict__ b, __half* __restrict__ outh)
{
    const int t   = blockIdx.x;
    const int tid = threadIdx.x;
    const float* xr = x + (size_t)t * HID;

    float v[8];
    float s = 0.f, s2 = 0.f;
#pragma unroll
    for (int i = 0; i < 8; i++) {
        v[i] = xr[tid + i * 256];
        s  += v[i];
        s2 += v[i] * v[i];
    }
#pragma unroll
    for (int o = 16; o; o >>= 1) {
        s  += __shfl_xor_sync(0xffffffffu, s,  o);
        s2 += __shfl_xor_sync(0xffffffffu, s2, o);
    }
    __shared__ float ss[8], ss2[8];
    if ((tid & 31) == 0) { ss[tid >> 5] = s; ss2[tid >> 5] = s2; }
    __syncthreads();
    if (tid < 32) {
        s  = (tid < 8) ? ss [tid] : 0.f;
        s2 = (tid < 8) ? ss2[tid] : 0.f;
#pragma unroll
        for (int o = 4; o; o >>= 1) {
            s  += __shfl_xor_sync(0xffffffffu, s,  o);
            s2 += __shfl_xor_sync(0xffffffffu, s2, o);
        }
        if (tid == 0) { ss[0] = s; ss2[0] = s2; }
    }
    __syncthreads();
    const float mean = ss[0] * (1.f / HID);
    const float var  = ss2[0] * (1.f / HID) - mean * mean;
    const float rstd = rsqrtf(var + LN_EPS);
    __half* orow = outh + (size_t)t * HID;
#pragma unroll
    for (int i = 0; i < 8; i++) {
        const int idx = tid + i * 256;
        const float y = (v[i] - mean) * rstd * w[idx] + b[idx];
        orow[idx] = __float2half_rn(y);
    }
}

// ---------------------------------------------------------------------------
// Partial RoPE on fp16 buffers: q2 row stride HID, k (in kv2) row stride kvs
// ---------------------------------------------------------------------------
__global__ void __launch_bounds__(256) rope_h_kernel(
    __half* __restrict__ q2, __half* __restrict__ k2,
    const int* __restrict__ pos_ids, int kvs)
{
    const int idx = blockIdx.x * blockDim.x + threadIdx.x;
    if (idx >= TT * NH * 8) return;
    const int i = idx & 7;
    const int h = (idx >> 3) & 31;
    const int t = idx >> 8;
    const int b = t / SS, s = t % SS;
    const int pos = pos_ids[b * SS + s];

    const float freq = powf(10000.0f, -(2.0f * (float)i) / (float)ROT);
    const float ang  = (float)pos * freq;
    float c, si;
    sincosf(ang, &si, &c);

    {
        const size_t base = (size_t)t * HID + h * HD;
        const float q0 = __half2float(q2[base + i]);
        const float q1 = __half2float(q2[base + i + 8]);
        q2[base + i]     = __float2half_rn(q0 * c - q1 * si);
        q2[base + i + 8] = __float2half_rn(q1 * c + q0 * si);
    }
    {
        const size_t base = (size_t)t * kvs + h * HD;
        const float k0 = __half2float(k2[base + i]);
        const float k1 = __half2float(k2[base + i + 8]);
        k2[base + i]     = __float2half_rn(k0 * c - k1 * si);
        k2[base + i + 8] = __float2half_rn(k1 * c + k0 * si);
    }
}

extern "C" void kernel_launch(void* const* d_in, const int* in_sizes, int n_in,
                              void* d_out, int out_size)
{
    const float* hidden = (const float*)d_in[0];
    const float* memory = (const float*)d_in[1];
    const float* mask   = (const float*)d_in[2];
    const int*   pos    = (const int*)  d_in[3];
    const float* Wq     = (const float*)d_in[4];
    const float* Wk     = (const float*)d_in[5];
    const float* Wv     = (const float*)d_in[6];
    const float* Wo     = (const float*)d_in[7];
    const float* ln1w   = (const float*)d_in[8];
    const float* ln1b   = (const float*)d_in[9];
    const float* ln2w   = (const float*)d_in[10];
    const float* ln2b   = (const float*)d_in[11];
    const float* gw     = (const float*)d_in[12];
    const float* uw     = (const float*)d_in[13];
    const float* dw     = (const float*)d_in[14];
    float* out = (float*)d_out;

    float *h;
    __half *q2, *kv2, *a2, *b2, *c2;
    cudaGetSymbolAddress((void**)&h,    g_h);
    cudaGetSymbolAddress((void**)&q2,   g_q2);
    cudaGetSymbolAddress((void**)&kv2,  g_kv2);
    cudaGetSymbolAddress((void**)&a2,   g_a2);
    cudaGetSymbolAddress((void**)&b2,   g_b2);
    cudaGetSymbolAddress((void**)&c2,   g_c2);

    cudaFuncSetAttribute(gemm2_kernel,
                         cudaFuncAttributeMaxDynamicSharedMemorySize, GEMM_DSMEM);
    cudaFuncSetAttribute(flash_attn_kernel,
                         cudaFuncAttributeMaxDynamicSharedMemorySize, FA_SMEM);

    const size_t HH = (size_t)HID * HID;

    auto gemm = [&](const __half* A, const __half* B,
                    const float* add, float* C, __half* O2,
                    int M, int N, int K2, int mode) {
        gemm2_kernel<<<dim3(N / 128, M / 128), 128, GEMM_DSMEM>>>(
            A, B, add, C, O2, M, N, K2, mode);
    };

    // weights + inputs to fp16
    conv4_kernel<<<dim3((unsigned)(HH / 8192), 4), 256>>>(Wq, Wk, Wv, Wo, b2);
    conv_kernel<<<(unsigned)((size_t)TT * HID / 8192), 256>>>(memory, c2);
    layernorm_h_kernel<<<TT, 256>>>(hidden, ln1w, ln1b, a2);

    // Q projection -> fp16 q2 ; K+V fused -> fp16 kv2
    gemm(a2, b2, nullptr, nullptr, q2, TT, HID, HID, 5);
    gemm(c2, b2 + HH, nullptr, nullptr, kv2, TT, 2 * HID, HID, 5);

    // RoPE on fp16
    rope_h_kernel<<<(TT * NH * 8) / 256, 256>>>(q2, kv2, pos, 2 * HID);

    // flash attention (fp16 Q/K/V) -> fp16 ctx into a2
    flash_attn_kernel<<<dim3(SS / 128, BB * NH), 256, FA_SMEM>>>(
        q2, kv2, kv2 + HID, mask, a2, 2 * HID);

    // O projection + residual (Wo at b2+3HH)
    gemm(a2, b2 + 3 * HH, hidden, h, nullptr, TT, HID, HID, 1);

    // LN2
    layernorm_h_kernel<<<TT, 256>>>(h, ln2w, ln2b, a2);

    // fused gate+up GEMM (interleaved weights), then down
    conv_il2_kernel<<<dim3((unsigned)((size_t)DFF * HID / 8192), 2), 256>>>(gw, uw, b2);
    gemm(a2, b2, nullptr, nullptr, c2, TT, 2 * DFF, HID, 4);
    conv_kernel<<<(unsigned)((size_t)HID * DFF / 8192), 256>>>(dw, b2);
    gemm(c2, b2, h, out, nullptr, TT, HID, DFF, 1);
}